// round 16
// baseline (speedup 1.0000x reference)
#include <cuda_runtime.h>
#include <cuda_bf16.h>
#include <math.h>
#include <stdint.h>

#define N_NODES 50000
#define N_EDGESC 400000
#define H 128
#define NT 2
#define FEAT 4
#define TILE_E 128

// ---------------- device scratch (no runtime allocation) ----------------
__device__ float g_h[N_NODES * H];
__device__ float g_agg[N_NODES * H];
__device__ float g_gi[N_NODES * 3 * H];
__device__ float g_gh[N_NODES * 3 * H];
__device__ float g_P1[2 * N_NODES * H];   // h @ W1_top per type
__device__ float g_P2[2 * N_NODES * H];   // h @ W1_bot per type
__device__ int   g_perm[N_EDGESC];
__device__ int   g_cnt[2];
__device__ int   g_cursor[2];
// W1 node-GEMM layout: [lt][half][n(128)][kw(64)] bf16x2 hi/lo
__device__ uint32_t g_WPB_hi[6 * 2 * 128 * 64];
__device__ uint32_t g_WPB_lo[6 * 2 * 128 * 64];
// W2 edge layout: [lt][n(128)][kw(64)]
__device__ uint32_t g_W2B_hi[6 * 128 * 64];
__device__ uint32_t g_W2B_lo[6 * 128 * 64];
// GRU weights: [sel(ih/hh)][l][n(384)][kw(64)]
__device__ uint32_t g_WGB_hi[2 * 3 * 384 * 64];
__device__ uint32_t g_WGB_lo[2 * 3 * 384 * 64];

__device__ __forceinline__ float sigm(float v) { return 1.0f / (1.0f + expf(-v)); }

__device__ __forceinline__ void split_pack(float x, float y, uint32_t& hi, uint32_t& lo) {
    __nv_bfloat162 h = __floats2bfloat162_rn(x, y);
    hi = reinterpret_cast<uint32_t&>(h);
    float rx = x - __low2float(h);
    float ry = y - __high2float(h);
    __nv_bfloat162 l = __floats2bfloat162_rn(rx, ry);
    lo = reinterpret_cast<uint32_t&>(l);
}

__device__ __forceinline__ void mma_bf16(float* c, uint32_t a0, uint32_t a1, uint32_t a2,
                                         uint32_t a3, uint32_t b0, uint32_t b1) {
    asm volatile(
        "mma.sync.aligned.m16n8k16.row.col.f32.bf16.bf16.f32 "
        "{%0,%1,%2,%3}, {%4,%5,%6,%7}, {%8,%9}, {%0,%1,%2,%3};"
        : "+f"(c[0]), "+f"(c[1]), "+f"(c[2]), "+f"(c[3])
        : "r"(a0), "r"(a1), "r"(a2), "r"(a3), "r"(b0), "r"(b1));
}

__device__ __forceinline__ void red2(float* p, float a, float b) {
    asm volatile("red.global.add.v2.f32 [%0], {%1, %2};" :: "l"(p), "f"(a), "f"(b) : "memory");
}

__device__ __forceinline__ void cp16(uint32_t saddr, const void* g) {
    asm volatile("cp.async.cg.shared.global [%0], [%1], 16;" :: "r"(saddr), "l"(g));
}
#define CP_COMMIT() asm volatile("cp.async.commit_group;" ::: "memory")
#define CP_WAIT0()  asm volatile("cp.async.wait_group 0;" ::: "memory")
#define CP_WAIT1()  asm volatile("cp.async.wait_group 1;" ::: "memory")

__device__ __forceinline__ uint32_t smem_u32(const void* p) {
    uint32_t a;
    asm("{ .reg .u64 t; cvta.to.shared.u64 t, %1; cvt.u32.u64 %0, t; }" : "=r"(a) : "l"(p));
    return a;
}

// ---------------- edge partition by type ----------------
__global__ void k_zero_cnt() { if (threadIdx.x < 2) g_cnt[threadIdx.x] = 0; }

__global__ void k_count(const int* __restrict__ et) {
    __shared__ int lc[2];
    if (threadIdx.x < 2) lc[threadIdx.x] = 0;
    __syncthreads();
    int e = blockIdx.x * blockDim.x + threadIdx.x;
    if (e < N_EDGESC) atomicAdd(&lc[et[e]], 1);
    __syncthreads();
    if (threadIdx.x < 2) atomicAdd(&g_cnt[threadIdx.x], lc[threadIdx.x]);
}

__global__ void k_seed() { g_cursor[0] = 0; g_cursor[1] = g_cnt[0]; }

__global__ void k_scatter(const int* __restrict__ et) {
    __shared__ int lc[2];
    __shared__ int base[2];
    if (threadIdx.x < 2) lc[threadIdx.x] = 0;
    __syncthreads();
    int e = blockIdx.x * blockDim.x + threadIdx.x;
    int t = 0, rank = 0;
    bool valid = (e < N_EDGESC);
    if (valid) { t = et[e]; rank = atomicAdd(&lc[t], 1); }
    __syncthreads();
    if (threadIdx.x < 2) base[threadIdx.x] = atomicAdd(&g_cursor[threadIdx.x], lc[threadIdx.x]);
    __syncthreads();
    if (valid) g_perm[base[t] + rank] = e;
}

// ---------------- weight prep ----------------
__global__ void k_prep_w(const float* __restrict__ W1, const float* __restrict__ W2) {
    int idx = blockIdx.x * blockDim.x + threadIdx.x;
    const int NW1 = 6 * 2 * 128 * 64;
    const int NW2 = 6 * 128 * 64;
    if (idx < NW1) {
        int lt = idx >> 14, rem = idx & 16383;
        int half = rem >> 13, rem2 = rem & 8191;
        int n = rem2 >> 6, kw = rem2 & 63;
        const float* base = W1 + (size_t)lt * 32768;
        int k = half * 128 + 2 * kw;
        float v0 = base[(size_t)k * 128 + n];
        float v1 = base[(size_t)(k + 1) * 128 + n];
        uint32_t hi, lo;
        split_pack(v0, v1, hi, lo);
        g_WPB_hi[idx] = hi; g_WPB_lo[idx] = lo;
    } else if (idx < NW1 + NW2) {
        int i2 = idx - NW1;
        int lt = i2 >> 13, rem = i2 & 8191;
        int n = rem >> 6, kw = rem & 63;
        const float* base = W2 + (size_t)lt * 16384;
        float v0 = base[(2 * kw) * 128 + n];
        float v1 = base[(2 * kw + 1) * 128 + n];
        uint32_t hi, lo;
        split_pack(v0, v1, hi, lo);
        int o = lt * 8192 + n * 64 + kw;
        g_W2B_hi[o] = hi; g_W2B_lo[o] = lo;
    }
}

__global__ void k_prep_gru(const float* __restrict__ Wih, const float* __restrict__ Whh) {
    int idx = blockIdx.x * blockDim.x + threadIdx.x;
    const int TOT = 2 * 3 * 384 * 64;
    if (idx >= TOT) return;
    int sel = idx / 73728, rem = idx % 73728;
    int l = rem / 24576, rem2 = rem % 24576;
    int n = rem2 >> 6, kw = rem2 & 63;
    const float* src = (sel ? Whh : Wih) + (size_t)l * H * 3 * H;
    float v0 = src[(2 * kw) * 384 + n];
    float v1 = src[(2 * kw + 1) * 384 + n];
    uint32_t hi, lo;
    split_pack(v0, v1, hi, lo);
    g_WGB_hi[idx] = hi;
    g_WGB_lo[idx] = lo;
}

// ---------------- h = relu(x @ W_in + b_in); zero agg for layer 0 ----------------
__global__ void k_init(const float* __restrict__ x, const float* __restrict__ Win,
                       const float* __restrict__ bin) {
    __shared__ float sW[FEAT * H];
    __shared__ float sb[H];
    for (int i = threadIdx.x; i < FEAT * H; i += blockDim.x) sW[i] = Win[i];
    if (threadIdx.x < H) sb[threadIdx.x] = bin[threadIdx.x];
    __syncthreads();
    int idx = blockIdx.x * blockDim.x + threadIdx.x;
    if (idx >= N_NODES * H) return;
    int n = idx >> 7, c = idx & 127;
    float4 xr = ((const float4*)x)[n];
    float v = sb[c] + xr.x * sW[c] + xr.y * sW[H + c] + xr.z * sW[2 * H + c] + xr.w * sW[3 * H + c];
    g_h[idx] = fmaxf(v, 0.0f);
    g_agg[idx] = 0.0f;
}

// ---------------- shared pipeline constants ----------------
#define A_STR 68
#define B_STR 20
#define F_AH 0
#define F_AL (128 * A_STR)
#define F_B  (2 * 128 * A_STR)
#define B_BUF_W (2 * 128 * B_STR)
#define F_META (F_B + 2 * B_BUF_W)
#define EDGE_SMEM ((F_META + 512) * 4)

#define A2_STR 20
#define G_AH 0
#define G_AL (128 * A2_STR)
#define G_B  (2 * 128 * A2_STR)
#define GB_BUF_W (2 * 128 * B_STR)
#define G_BIAS (G_B + 2 * GB_BUF_W)
#define GRU_SMEM ((G_BIAS + 128) * 4)

// ---------------- node precompute: P1/P2 = h @ W1_{top,bot} per type ----------------
__global__ __launch_bounds__(256, 2)
void k_node_pre(int l) {
    extern __shared__ uint32_t smw[];
    uint32_t* sAh = smw + G_AH;
    uint32_t* sAl = smw + G_AL;
    const uint32_t su = smem_u32(smw);

    int tid = threadIdx.x;
    int w = tid >> 5, lane = tid & 31;
    int gid = lane >> 2, tig = lane & 3;

    int t = blockIdx.y >> 1, half = blockIdx.y & 1;
    const uint32_t* wbh = g_WPB_hi + ((size_t)(l * NT + t) * 2 + half) * 8192;
    const uint32_t* wbl = g_WPB_lo + ((size_t)(l * NT + t) * 2 + half) * 8192;
    float* C = (half ? g_P2 : g_P1) + (size_t)t * N_NODES * H;

    int m0 = blockIdx.x * 128;
    int nB = tid >> 1, offB = (tid & 1) * 8;

    {
        uint32_t dst = su + (G_B + nB * B_STR + offB) * 4;
        const uint32_t* gh_ = wbh + (size_t)nB * 64 + offB;
        const uint32_t* gl_ = wbl + (size_t)nB * 64 + offB;
        cp16(dst, gh_); cp16(dst + 16, gh_ + 4);
        cp16(dst + 128 * B_STR * 4, gl_); cp16(dst + 128 * B_STR * 4 + 16, gl_ + 4);
        CP_COMMIT();
    }

    float acc[16][4];
#pragma unroll
    for (int j = 0; j < 16; ++j)
#pragma unroll
        for (int q = 0; q < 4; ++q) acc[j][q] = 0.f;

    int rA0 = w * 16 + gid;
    int rA1 = rA0 + 8;

    float4 aCur[4], aNxt[4];
#pragma unroll
    for (int i = 0; i < 4; ++i) {
        int i0 = tid + i * 256, r = i0 >> 3, q = i0 & 7;
        int m = m0 + r;
        aCur[i] = (m < N_NODES) ? *(const float4*)(g_h + (size_t)m * H + q * 4)
                                : make_float4(0.f, 0.f, 0.f, 0.f);
    }

    for (int kc = 0; kc < 4; ++kc) {
        int buf = kc & 1;
#pragma unroll
        for (int i = 0; i < 4; ++i) {
            int i0 = tid + i * 256, r = i0 >> 3, q = i0 & 7;
            uint32_t h0, l0, h1, l1;
            split_pack(aCur[i].x, aCur[i].y, h0, l0);
            split_pack(aCur[i].z, aCur[i].w, h1, l1);
            *(uint2*)(sAh + r * A2_STR + q * 2) = make_uint2(h0, h1);
            *(uint2*)(sAl + r * A2_STR + q * 2) = make_uint2(l0, l1);
        }
        if (kc < 3) {
            int kn = kc + 1;
#pragma unroll
            for (int i = 0; i < 4; ++i) {
                int i0 = tid + i * 256, r = i0 >> 3, q = i0 & 7;
                int m = m0 + r;
                aNxt[i] = (m < N_NODES)
                    ? *(const float4*)(g_h + (size_t)m * H + kn * 32 + q * 4)
                    : make_float4(0.f, 0.f, 0.f, 0.f);
            }
            uint32_t dst = su + (G_B + (buf ^ 1) * GB_BUF_W + nB * B_STR + offB) * 4;
            const uint32_t* gh_ = wbh + (size_t)nB * 64 + kn * 16 + offB;
            const uint32_t* gl_ = wbl + (size_t)nB * 64 + kn * 16 + offB;
            cp16(dst, gh_); cp16(dst + 16, gh_ + 4);
            cp16(dst + 128 * B_STR * 4, gl_); cp16(dst + 128 * B_STR * 4 + 16, gl_ + 4);
            CP_COMMIT();
            CP_WAIT1();
        } else {
            CP_WAIT0();
        }
        __syncthreads();
        const uint32_t* sBh = smw + G_B + buf * GB_BUF_W;
        const uint32_t* sBl = sBh + 128 * B_STR;
#pragma unroll
        for (int s = 0; s < 2; ++s) {
            int kwb = 8 * s;
            uint32_t ah0 = sAh[rA0 * A2_STR + kwb + tig];
            uint32_t ah1 = sAh[rA1 * A2_STR + kwb + tig];
            uint32_t ah2 = sAh[rA0 * A2_STR + kwb + tig + 4];
            uint32_t ah3 = sAh[rA1 * A2_STR + kwb + tig + 4];
            uint32_t al0 = sAl[rA0 * A2_STR + kwb + tig];
            uint32_t al1 = sAl[rA1 * A2_STR + kwb + tig];
            uint32_t al2 = sAl[rA0 * A2_STR + kwb + tig + 4];
            uint32_t al3 = sAl[rA1 * A2_STR + kwb + tig + 4];
#pragma unroll
            for (int j = 0; j < 16; ++j) {
                int nb = (j * 8 + gid) * B_STR + kwb + tig;
                uint32_t bh0 = sBh[nb], bh1 = sBh[nb + 4];
                uint32_t bl0 = sBl[nb], bl1 = sBl[nb + 4];
                mma_bf16(acc[j], ah0, ah1, ah2, ah3, bh0, bh1);
                mma_bf16(acc[j], al0, al1, al2, al3, bh0, bh1);
                mma_bf16(acc[j], ah0, ah1, ah2, ah3, bl0, bl1);
            }
        }
        __syncthreads();
#pragma unroll
        for (int i = 0; i < 4; ++i) aCur[i] = aNxt[i];
    }

    int mg0 = m0 + rA0;
    int mg1 = m0 + rA1;
#pragma unroll
    for (int j = 0; j < 16; ++j) {
        int col = j * 8 + 2 * tig;
        if (mg0 < N_NODES)
            *(float2*)(C + (size_t)mg0 * H + col) = make_float2(acc[j][0], acc[j][1]);
        if (mg1 < N_NODES)
            *(float2*)(C + (size_t)mg1 * H + col) = make_float2(acc[j][2], acc[j][3]);
    }
}

// ---------------- edge kernel: pipelined gather from P1/P2 + GEMM2 ----------------
__global__ __launch_bounds__(256, 2)
void k_edge_tc(const int* __restrict__ edge_index,
               const float* __restrict__ b1, const float* __restrict__ b2, int l) {
    extern __shared__ uint32_t smw[];
    uint32_t* sAh = smw + F_AH;
    uint32_t* sAl = smw + F_AL;
    int*   sSrc = (int*)(smw + F_META);
    int*   sDst = sSrc + 128;
    float* sB1  = (float*)(sDst + 128);
    float* sB2  = sB1 + 128;
    const uint32_t su = smem_u32(smw);

    int tid = threadIdx.x;
    int w = tid >> 5, lane = tid & 31;
    int gid = lane >> 2, tig = lane & 3;

    int cnt0 = g_cnt[0];
    int nb0 = (cnt0 + TILE_E - 1) / TILE_E;
    int type, start, cnt, permBase;
    if ((int)blockIdx.x < nb0) {
        type = 0; start = blockIdx.x * TILE_E; cnt = cnt0; permBase = 0;
    } else {
        type = 1; start = ((int)blockIdx.x - nb0) * TILE_E;
        cnt = N_EDGESC - cnt0; permBase = cnt0;
        if (start >= cnt) return;
    }
    int lt = l * NT + type;

    const uint32_t* w2h = g_W2B_hi + (size_t)lt * 8192;
    const uint32_t* w2l = g_W2B_lo + (size_t)lt * 8192;
    const float* P1t = g_P1 + (size_t)type * N_NODES * H;
    const float* P2t = g_P2 + (size_t)type * N_NODES * H;

    int nB = tid >> 1, offB = (tid & 1) * 8;

    // issue B2(0) into buf 0
    {
        uint32_t dst = su + (F_B + nB * B_STR + offB) * 4;
        const uint32_t* gh_ = w2h + nB * 64 + offB;
        const uint32_t* gl_ = w2l + nB * 64 + offB;
        cp16(dst, gh_); cp16(dst + 16, gh_ + 4);
        cp16(dst + 128 * B_STR * 4, gl_); cp16(dst + 128 * B_STR * 4 + 16, gl_ + 4);
        CP_COMMIT();
    }

    if (tid < 128) {
        int g = start + tid; int s = -1, d = -1;
        if (g < cnt) { int e = g_perm[permBase + g]; s = edge_index[e]; d = edge_index[N_EDGESC + e]; }
        sSrc[tid] = s;
        sDst[tid] = d;
    } else {
        int c = tid - 128;
        sB1[c] = b1[lt * H + c];
        sB2[c] = b2[lt * H + c];
    }
    __syncthreads();

    float acc[16][4];
#pragma unroll
    for (int j = 0; j < 16; ++j)
#pragma unroll
        for (int q = 0; q < 4; ++q) acc[j][q] = 0.f;

    int rA0 = w * 16 + gid;
    int rA1 = rA0 + 8;

    // per-thread gather positions: i0 = tid + i*256 of 1024 = 128 rows x 8 q
    int rG[4], qG[4];
#pragma unroll
    for (int i = 0; i < 4; ++i) { int i0 = tid + i * 256; rG[i] = i0 >> 3; qG[i] = i0 & 7; }

    // prefetch chunk 0: sum = P1[src] + P2[dst] for cols q*4 (c4 = q)
    float4 aCur[4], aNxt[4];
#pragma unroll
    for (int i = 0; i < 4; ++i) {
        int s = sSrc[rG[i]], d = sDst[rG[i]];
        if (s >= 0) {
            float4 v1 = *(const float4*)(P1t + (size_t)s * H + qG[i] * 4);
            float4 v2 = *(const float4*)(P2t + (size_t)d * H + qG[i] * 4);
            aCur[i] = make_float4(v1.x + v2.x, v1.y + v2.y, v1.z + v2.z, v1.w + v2.w);
        } else aCur[i] = make_float4(0.f, 0.f, 0.f, 0.f);
    }

    // GEMM2: 4 K-chunks, pipelined A (registers) + B (cp.async)
    for (int kc = 0; kc < 4; ++kc) {
        int buf = kc & 1;
        // store A(kc): hv = relu(sum + b1), split-pack at kw = kc*16 + q*2
#pragma unroll
        for (int i = 0; i < 4; ++i) {
            int c4 = kc * 8 + qG[i];
            float4 bb = *(const float4*)(sB1 + c4 * 4);
            bool valid = (sSrc[rG[i]] >= 0);
            float hx = valid ? fmaxf(aCur[i].x + bb.x, 0.f) : 0.f;
            float hy = valid ? fmaxf(aCur[i].y + bb.y, 0.f) : 0.f;
            float hz = valid ? fmaxf(aCur[i].z + bb.z, 0.f) : 0.f;
            float hw = valid ? fmaxf(aCur[i].w + bb.w, 0.f) : 0.f;
            uint32_t h0, l0, h1, l1;
            split_pack(hx, hy, h0, l0);
            split_pack(hz, hw, h1, l1);
            *(uint2*)(sAh + rG[i] * A_STR + kc * 16 + qG[i] * 2) = make_uint2(h0, h1);
            *(uint2*)(sAl + rG[i] * A_STR + kc * 16 + qG[i] * 2) = make_uint2(l0, l1);
        }
        if (kc < 3) {
            int kn = kc + 1;
            // prefetch A(kc+1) sums
#pragma unroll
            for (int i = 0; i < 4; ++i) {
                int s = sSrc[rG[i]], d = sDst[rG[i]];
                if (s >= 0) {
                    int c4 = kn * 8 + qG[i];
                    float4 v1 = *(const float4*)(P1t + (size_t)s * H + c4 * 4);
                    float4 v2 = *(const float4*)(P2t + (size_t)d * H + c4 * 4);
                    aNxt[i] = make_float4(v1.x + v2.x, v1.y + v2.y, v1.z + v2.z, v1.w + v2.w);
                } else aNxt[i] = make_float4(0.f, 0.f, 0.f, 0.f);
            }
            // issue B(kc+1)
            uint32_t dst = su + (F_B + (buf ^ 1) * B_BUF_W + nB * B_STR + offB) * 4;
            const uint32_t* gh_ = w2h + nB * 64 + kn * 16 + offB;
            const uint32_t* gl_ = w2l + nB * 64 + kn * 16 + offB;
            cp16(dst, gh_); cp16(dst + 16, gh_ + 4);
            cp16(dst + 128 * B_STR * 4, gl_); cp16(dst + 128 * B_STR * 4 + 16, gl_ + 4);
            CP_COMMIT();
            CP_WAIT1();
        } else {
            CP_WAIT0();
        }
        __syncthreads();
        const uint32_t* sBh = smw + F_B + buf * B_BUF_W;
        const uint32_t* sBl = sBh + 128 * B_STR;
#pragma unroll
        for (int s = 0; s < 2; ++s) {
            int kwb = kc * 16 + 8 * s;
            uint32_t ah0 = sAh[rA0 * A_STR + kwb + tig];
            uint32_t ah1 = sAh[rA1 * A_STR + kwb + tig];
            uint32_t ah2 = sAh[rA0 * A_STR + kwb + tig + 4];
            uint32_t ah3 = sAh[rA1 * A_STR + kwb + tig + 4];
            uint32_t al0 = sAl[rA0 * A_STR + kwb + tig];
            uint32_t al1 = sAl[rA1 * A_STR + kwb + tig];
            uint32_t al2 = sAl[rA0 * A_STR + kwb + tig + 4];
            uint32_t al3 = sAl[rA1 * A_STR + kwb + tig + 4];
#pragma unroll
            for (int j = 0; j < 16; ++j) {
                int nb = (j * 8 + gid) * B_STR + 8 * s + tig;
                uint32_t bh0 = sBh[nb], bh1 = sBh[nb + 4];
                uint32_t bl0 = sBl[nb], bl1 = sBl[nb + 4];
                mma_bf16(acc[j], ah0, ah1, ah2, ah3, bh0, bh1);
                mma_bf16(acc[j], al0, al1, al2, al3, bh0, bh1);
                mma_bf16(acc[j], ah0, ah1, ah2, ah3, bl0, bl1);
            }
        }
        __syncthreads();
#pragma unroll
        for (int i = 0; i < 4; ++i) aCur[i] = aNxt[i];
    }

    // epilogue: msgs = acc + b2 -> red into agg[dst]
    int d0 = sDst[rA0];
    int d1 = sDst[rA1];
#pragma unroll
    for (int j = 0; j < 16; ++j) {
        int col = j * 8 + 2 * tig;
        float ba = sB2[col], bb = sB2[col + 1];
        if (d0 >= 0) red2(g_agg + (size_t)d0 * H + col, acc[j][0] + ba, acc[j][1] + bb);
        if (d1 >= 0) red2(g_agg + (size_t)d1 * H + col, acc[j][2] + ba, acc[j][3] + bb);
    }
}

// ---------------- GRU GEMMs (R13 proven version) ----------------
__global__ __launch_bounds__(256, 2)
void k_gru_tc(const float* __restrict__ bih, const float* __restrict__ bhh, int l) {
    extern __shared__ uint32_t smw[];
    uint32_t* sAh = smw + G_AH;
    uint32_t* sAl = smw + G_AL;
    float* sBias = (float*)(smw + G_BIAS);
    const uint32_t su = smem_u32(smw);

    int tid = threadIdx.x;
    int w = tid >> 5, lane = tid & 31;
    int gid = lane >> 2, tig = lane & 3;

    int sel = blockIdx.z;
    const float* A = sel ? g_h : g_agg;
    float* C = sel ? g_gh : g_gi;
    const float* b = (sel ? bhh : bih) + l * 3 * H;
    const uint32_t* wbh = g_WGB_hi + ((size_t)sel * 3 + l) * 384 * 64;
    const uint32_t* wbl = g_WGB_lo + ((size_t)sel * 3 + l) * 384 * 64;

    int m0 = blockIdx.x * 128;
    int c0 = blockIdx.y * 128;

    int nB = tid >> 1, offB = (tid & 1) * 8;

    {
        uint32_t dst = su + (G_B + nB * B_STR + offB) * 4;
        const uint32_t* gh_ = wbh + (size_t)(c0 + nB) * 64 + offB;
        const uint32_t* gl_ = wbl + (size_t)(c0 + nB) * 64 + offB;
        cp16(dst, gh_); cp16(dst + 16, gh_ + 4);
        cp16(dst + 128 * B_STR * 4, gl_); cp16(dst + 128 * B_STR * 4 + 16, gl_ + 4);
        CP_COMMIT();
    }

    if (tid < 128) sBias[tid] = b[c0 + tid];

    float acc[16][4];
#pragma unroll
    for (int j = 0; j < 16; ++j)
#pragma unroll
        for (int q = 0; q < 4; ++q) acc[j][q] = 0.f;

    int rA0 = w * 16 + gid;
    int rA1 = rA0 + 8;

    float4 aCur[4], aNxt[4];
#pragma unroll
    for (int i = 0; i < 4; ++i) {
        int i0 = tid + i * 256, r = i0 >> 3, q = i0 & 7;
        int m = m0 + r;
        aCur[i] = (m < N_NODES) ? *(const float4*)(A + (size_t)m * H + q * 4)
                                : make_float4(0.f, 0.f, 0.f, 0.f);
    }

    for (int kc = 0; kc < 4; ++kc) {
        int buf = kc & 1;
#pragma unroll
        for (int i = 0; i < 4; ++i) {
            int i0 = tid + i * 256, r = i0 >> 3, q = i0 & 7;
            uint32_t h0, l0, h1, l1;
            split_pack(aCur[i].x, aCur[i].y, h0, l0);
            split_pack(aCur[i].z, aCur[i].w, h1, l1);
            *(uint2*)(sAh + r * A2_STR + q * 2) = make_uint2(h0, h1);
            *(uint2*)(sAl + r * A2_STR + q * 2) = make_uint2(l0, l1);
        }
        if (kc < 3) {
            int kn = kc + 1;
#pragma unroll
            for (int i = 0; i < 4; ++i) {
                int i0 = tid + i * 256, r = i0 >> 3, q = i0 & 7;
                int m = m0 + r;
                aNxt[i] = (m < N_NODES)
                    ? *(const float4*)(A + (size_t)m * H + kn * 32 + q * 4)
                    : make_float4(0.f, 0.f, 0.f, 0.f);
            }
            uint32_t dst = su + (G_B + (buf ^ 1) * GB_BUF_W + nB * B_STR + offB) * 4;
            const uint32_t* gh_ = wbh + (size_t)(c0 + nB) * 64 + kn * 16 + offB;
            const uint32_t* gl_ = wbl + (size_t)(c0 + nB) * 64 + kn * 16 + offB;
            cp16(dst, gh_); cp16(dst + 16, gh_ + 4);
            cp16(dst + 128 * B_STR * 4, gl_); cp16(dst + 128 * B_STR * 4 + 16, gl_ + 4);
            CP_COMMIT();
            CP_WAIT1();
        } else {
            CP_WAIT0();
        }
        __syncthreads();
        const uint32_t* sBh = smw + G_B + buf * GB_BUF_W;
        const uint32_t* sBl = sBh + 128 * B_STR;
#pragma unroll
        for (int s = 0; s < 2; ++s) {
            int kwb = 8 * s;
            uint32_t ah0 = sAh[rA0 * A2_STR + kwb + tig];
            uint32_t ah1 = sAh[rA1 * A2_STR + kwb + tig];
            uint32_t ah2 = sAh[rA0 * A2_STR + kwb + tig + 4];
            uint32_t ah3 = sAh[rA1 * A2_STR + kwb + tig + 4];
            uint32_t al0 = sAl[rA0 * A2_STR + kwb + tig];
            uint32_t al1 = sAl[rA1 * A2_STR + kwb + tig];
            uint32_t al2 = sAl[rA0 * A2_STR + kwb + tig + 4];
            uint32_t al3 = sAl[rA1 * A2_STR + kwb + tig + 4];
#pragma unroll
            for (int j = 0; j < 16; ++j) {
                int nb = (j * 8 + gid) * B_STR + kwb + tig;
                uint32_t bh0 = sBh[nb], bh1 = sBh[nb + 4];
                uint32_t bl0 = sBl[nb], bl1 = sBl[nb + 4];
                mma_bf16(acc[j], ah0, ah1, ah2, ah3, bh0, bh1);
                mma_bf16(acc[j], al0, al1, al2, al3, bh0, bh1);
                mma_bf16(acc[j], ah0, ah1, ah2, ah3, bl0, bl1);
            }
        }
        __syncthreads();
#pragma unroll
        for (int i = 0; i < 4; ++i) aCur[i] = aNxt[i];
    }

    int mg0 = m0 + rA0;
    int mg1 = m0 + rA1;
#pragma unroll
    for (int j = 0; j < 16; ++j) {
        int col = j * 8 + 2 * tig;
        float ba = sBias[col], bb = sBias[col + 1];
        if (mg0 < N_NODES)
            *(float2*)(C + (size_t)mg0 * 384 + c0 + col) =
                make_float2(acc[j][0] + ba, acc[j][1] + bb);
        if (mg1 < N_NODES)
            *(float2*)(C + (size_t)mg1 * 384 + c0 + col) =
                make_float2(acc[j][2] + ba, acc[j][3] + bb);
    }
}

__global__ void k_gru_combine() {
    int idx = blockIdx.x * blockDim.x + threadIdx.x;
    if (idx >= N_NODES * H) return;
    int n = idx >> 7, c = idx & 127;
    const float* gi = g_gi + (size_t)n * 384;
    const float* gh = g_gh + (size_t)n * 384;
    float r = sigm(gi[c] + gh[c]);
    float z = sigm(gi[128 + c] + gh[128 + c]);
    float nn = tanhf(gi[256 + c] + r * gh[256 + c]);
    g_h[idx] = (1.0f - z) * nn + z * g_h[idx];
    g_agg[idx] = 0.0f;
}

// ---------------- readout ----------------
__global__ __launch_bounds__(256)
void k_readout(const float* __restrict__ Wr1, const float* __restrict__ br1,
               const float* __restrict__ Wr2, const float* __restrict__ br2,
               float* __restrict__ out, int nd) {
    extern __shared__ float smemf[];
    float* sW1 = smemf;
    float* sb1 = sW1 + H * H;
    float* sW2 = sb1 + H;
    float* sHrow = sW2 + H;

    for (int t = threadIdx.x; t < (H * H) / 4; t += blockDim.x)
        ((float4*)sW1)[t] = ((const float4*)Wr1)[t];
    if (threadIdx.x < H) {
        sb1[threadIdx.x] = br1[threadIdx.x];
        sW2[threadIdx.x] = Wr2[threadIdx.x];
    }
    __syncthreads();

    int w = threadIdx.x >> 5, lane = threadIdx.x & 31;
    float* myrow = sHrow + w * H;
    float b2v = br2[0];

    for (int n = blockIdx.x * 8 + w; n < nd; n += gridDim.x * 8) {
        ((float4*)myrow)[lane] = ((const float4*)(g_h + (size_t)n * H))[lane];
        __syncwarp();
        float hid0 = 0.f, hid1 = 0.f, hid2 = 0.f, hid3 = 0.f;
#pragma unroll 4
        for (int k = 0; k < H; ++k) {
            float a = myrow[k];
            float4 wv = ((const float4*)sW1)[k * 32 + lane];
            hid0 += a * wv.x; hid1 += a * wv.y; hid2 += a * wv.z; hid3 += a * wv.w;
        }
        float4 w2 = ((const float4*)sW2)[lane];
        float p = fmaxf(hid0 + sb1[lane * 4 + 0], 0.f) * w2.x
                + fmaxf(hid1 + sb1[lane * 4 + 1], 0.f) * w2.y
                + fmaxf(hid2 + sb1[lane * 4 + 2], 0.f) * w2.z
                + fmaxf(hid3 + sb1[lane * 4 + 3], 0.f) * w2.w;
#pragma unroll
        for (int o = 16; o > 0; o >>= 1) p += __shfl_down_sync(0xffffffffu, p, o);
        if (lane == 0) out[n] = p + b2v;
        __syncwarp();
    }
}

// ---------------- launch ----------------
extern "C" void kernel_launch(void* const* d_in, const int* in_sizes, int n_in,
                              void* d_out, int out_size) {
    int base = (n_in >= 18) ? 4 : 3;
    const float* x          = (const float*)d_in[0];
    const int*   edge_index = (const int*)d_in[1];
    const int*   edge_type  = (const int*)d_in[2];
    const float* W_in = (const float*)d_in[base + 0];
    const float* b_in = (const float*)d_in[base + 1];
    const float* W1   = (const float*)d_in[base + 2];
    const float* b1   = (const float*)d_in[base + 3];
    const float* W2   = (const float*)d_in[base + 4];
    const float* b2   = (const float*)d_in[base + 5];
    const float* W_ih = (const float*)d_in[base + 6];
    const float* b_ih = (const float*)d_in[base + 7];
    const float* W_hh = (const float*)d_in[base + 8];
    const float* b_hh = (const float*)d_in[base + 9];
    const float* Wr1  = (const float*)d_in[base + 10];
    const float* br1  = (const float*)d_in[base + 11];
    const float* Wr2  = (const float*)d_in[base + 12];
    const float* br2  = (const float*)d_in[base + 13];
    float* out = (float*)d_out;

    const int READ_SMEM = (128 * 128 + 128 + 128 + 8 * 128) * 4;
    cudaFuncSetAttribute(k_edge_tc,  cudaFuncAttributeMaxDynamicSharedMemorySize, EDGE_SMEM);
    cudaFuncSetAttribute(k_node_pre, cudaFuncAttributeMaxDynamicSharedMemorySize, GRU_SMEM);
    cudaFuncSetAttribute(k_gru_tc,   cudaFuncAttributeMaxDynamicSharedMemorySize, GRU_SMEM);
    cudaFuncSetAttribute(k_readout,  cudaFuncAttributeMaxDynamicSharedMemorySize, READ_SMEM);

    k_zero_cnt<<<1, 32>>>();
    k_count<<<(N_EDGESC + 255) / 256, 256>>>(edge_type);
    k_seed<<<1, 1>>>();
    k_scatter<<<(N_EDGESC + 255) / 256, 256>>>(edge_type);

    const int NPW = 6 * 2 * 128 * 64 + 6 * 128 * 64;
    k_prep_w<<<(NPW + 255) / 256, 256>>>(W1, W2);
    k_prep_gru<<<(2 * 3 * 384 * 64 + 255) / 256, 256>>>(W_ih, W_hh);
    k_init<<<(N_NODES * H + 255) / 256, 256>>>(x, W_in, b_in);

    const int NEL = N_NODES * H;
    const int EDGE_BLOCKS = N_EDGESC / TILE_E + 2;
    for (int l = 0; l < 3; ++l) {
        dim3 gp((N_NODES + 127) / 128, 4);
        k_node_pre<<<gp, 256, GRU_SMEM>>>(l);
        k_edge_tc<<<EDGE_BLOCKS, 256, EDGE_SMEM>>>(edge_index, b1, b2, l);
        dim3 gg((N_NODES + 127) / 128, 3, 2);
        k_gru_tc<<<gg, 256, GRU_SMEM>>>(b_ih, b_hh, l);
        k_gru_combine<<<(NEL + 255) / 256, 256>>>();
    }

    k_readout<<<625, 256, READ_SMEM>>>(Wr1, br1, Wr2, br2, out, out_size);
}

// round 17
// speedup vs baseline: 1.0097x; 1.0097x over previous
#include <cuda_runtime.h>
#include <cuda_bf16.h>
#include <math.h>
#include <stdint.h>

#define N_NODES 50000
#define N_EDGESC 400000
#define H 128
#define NT 2
#define FEAT 4
#define TILE_E 128

// ---------------- device scratch (no runtime allocation) ----------------
__device__ float g_h[N_NODES * H];
__device__ float g_agg[N_NODES * H];
__device__ float g_gi[N_NODES * 3 * H];
__device__ float g_gh[N_NODES * 3 * H];
__device__ float g_P1[2 * N_NODES * H];
__device__ float g_P2[2 * N_NODES * H];
// packed activations: [m][kw(64)] bf16x2 hi/lo
__device__ uint32_t g_hB_hi[N_NODES * 64];
__device__ uint32_t g_hB_lo[N_NODES * 64];
__device__ uint32_t g_aggB_hi[N_NODES * 64];
__device__ uint32_t g_aggB_lo[N_NODES * 64];
__device__ int   g_perm[N_EDGESC];
__device__ int   g_cnt[2];
__device__ int   g_cursor[2];
// W1 node-GEMM layout: [lt][half][n(128)][kw(64)]
__device__ uint32_t g_WPB_hi[6 * 2 * 128 * 64];
__device__ uint32_t g_WPB_lo[6 * 2 * 128 * 64];
// W2 edge layout: [lt][n(128)][kw(64)]
__device__ uint32_t g_W2B_hi[6 * 128 * 64];
__device__ uint32_t g_W2B_lo[6 * 128 * 64];
// GRU weights: [sel(ih/hh)][l][n(384)][kw(64)]
__device__ uint32_t g_WGB_hi[2 * 3 * 384 * 64];
__device__ uint32_t g_WGB_lo[2 * 3 * 384 * 64];

__device__ __forceinline__ float sigm(float v) { return 1.0f / (1.0f + expf(-v)); }

__device__ __forceinline__ void split_pack(float x, float y, uint32_t& hi, uint32_t& lo) {
    __nv_bfloat162 h = __floats2bfloat162_rn(x, y);
    hi = reinterpret_cast<uint32_t&>(h);
    float rx = x - __low2float(h);
    float ry = y - __high2float(h);
    __nv_bfloat162 l = __floats2bfloat162_rn(rx, ry);
    lo = reinterpret_cast<uint32_t&>(l);
}

__device__ __forceinline__ void mma_bf16(float* c, uint32_t a0, uint32_t a1, uint32_t a2,
                                         uint32_t a3, uint32_t b0, uint32_t b1) {
    asm volatile(
        "mma.sync.aligned.m16n8k16.row.col.f32.bf16.bf16.f32 "
        "{%0,%1,%2,%3}, {%4,%5,%6,%7}, {%8,%9}, {%0,%1,%2,%3};"
        : "+f"(c[0]), "+f"(c[1]), "+f"(c[2]), "+f"(c[3])
        : "r"(a0), "r"(a1), "r"(a2), "r"(a3), "r"(b0), "r"(b1));
}

__device__ __forceinline__ void red2(float* p, float a, float b) {
    asm volatile("red.global.add.v2.f32 [%0], {%1, %2};" :: "l"(p), "f"(a), "f"(b) : "memory");
}

__device__ __forceinline__ void cp16(uint32_t saddr, const void* g) {
    asm volatile("cp.async.cg.shared.global [%0], [%1], 16;" :: "r"(saddr), "l"(g));
}
#define CP_COMMIT() asm volatile("cp.async.commit_group;" ::: "memory")
#define CP_WAIT0()  asm volatile("cp.async.wait_group 0;" ::: "memory")
#define CP_WAIT1()  asm volatile("cp.async.wait_group 1;" ::: "memory")

__device__ __forceinline__ uint32_t smem_u32(const void* p) {
    uint32_t a;
    asm("{ .reg .u64 t; cvta.to.shared.u64 t, %1; cvt.u32.u64 %0, t; }" : "=r"(a) : "l"(p));
    return a;
}

// ---------------- edge partition by type ----------------
__global__ void k_zero_cnt() { if (threadIdx.x < 2) g_cnt[threadIdx.x] = 0; }

__global__ void k_count(const int* __restrict__ et) {
    __shared__ int lc[2];
    if (threadIdx.x < 2) lc[threadIdx.x] = 0;
    __syncthreads();
    int e = blockIdx.x * blockDim.x + threadIdx.x;
    if (e < N_EDGESC) atomicAdd(&lc[et[e]], 1);
    __syncthreads();
    if (threadIdx.x < 2) atomicAdd(&g_cnt[threadIdx.x], lc[threadIdx.x]);
}

__global__ void k_seed() { g_cursor[0] = 0; g_cursor[1] = g_cnt[0]; }

__global__ void k_scatter(const int* __restrict__ et) {
    __shared__ int lc[2];
    __shared__ int base[2];
    if (threadIdx.x < 2) lc[threadIdx.x] = 0;
    __syncthreads();
    int e = blockIdx.x * blockDim.x + threadIdx.x;
    int t = 0, rank = 0;
    bool valid = (e < N_EDGESC);
    if (valid) { t = et[e]; rank = atomicAdd(&lc[t], 1); }
    __syncthreads();
    if (threadIdx.x < 2) base[threadIdx.x] = atomicAdd(&g_cursor[threadIdx.x], lc[threadIdx.x]);
    __syncthreads();
    if (valid) g_perm[base[t] + rank] = e;
}

// ---------------- weight prep ----------------
__global__ void k_prep_w(const float* __restrict__ W1, const float* __restrict__ W2) {
    int idx = blockIdx.x * blockDim.x + threadIdx.x;
    const int NW1 = 6 * 2 * 128 * 64;
    const int NW2 = 6 * 128 * 64;
    if (idx < NW1) {
        int lt = idx >> 14, rem = idx & 16383;
        int half = rem >> 13, rem2 = rem & 8191;
        int n = rem2 >> 6, kw = rem2 & 63;
        const float* base = W1 + (size_t)lt * 32768;
        int k = half * 128 + 2 * kw;
        float v0 = base[(size_t)k * 128 + n];
        float v1 = base[(size_t)(k + 1) * 128 + n];
        uint32_t hi, lo;
        split_pack(v0, v1, hi, lo);
        g_WPB_hi[idx] = hi; g_WPB_lo[idx] = lo;
    } else if (idx < NW1 + NW2) {
        int i2 = idx - NW1;
        int lt = i2 >> 13, rem = i2 & 8191;
        int n = rem >> 6, kw = rem & 63;
        const float* base = W2 + (size_t)lt * 16384;
        float v0 = base[(2 * kw) * 128 + n];
        float v1 = base[(2 * kw + 1) * 128 + n];
        uint32_t hi, lo;
        split_pack(v0, v1, hi, lo);
        int o = lt * 8192 + n * 64 + kw;
        g_W2B_hi[o] = hi; g_W2B_lo[o] = lo;
    }
}

__global__ void k_prep_gru(const float* __restrict__ Wih, const float* __restrict__ Whh) {
    int idx = blockIdx.x * blockDim.x + threadIdx.x;
    const int TOT = 2 * 3 * 384 * 64;
    if (idx >= TOT) return;
    int sel = idx / 73728, rem = idx % 73728;
    int l = rem / 24576, rem2 = rem % 24576;
    int n = rem2 >> 6, kw = rem2 & 63;
    const float* src = (sel ? Whh : Wih) + (size_t)l * H * 3 * H;
    float v0 = src[(2 * kw) * 384 + n];
    float v1 = src[(2 * kw + 1) * 384 + n];
    uint32_t hi, lo;
    split_pack(v0, v1, hi, lo);
    g_WGB_hi[idx] = hi;
    g_WGB_lo[idx] = lo;
}

// ---------------- init: h = relu(x@Win+bin), pack h, zero agg ----------------
__global__ void k_init(const float* __restrict__ x, const float* __restrict__ Win,
                       const float* __restrict__ bin) {
    __shared__ float sW[FEAT * H];
    __shared__ float sb[H];
    for (int i = threadIdx.x; i < FEAT * H; i += blockDim.x) sW[i] = Win[i];
    if (threadIdx.x < H) sb[threadIdx.x] = bin[threadIdx.x];
    __syncthreads();
    int idx = blockIdx.x * blockDim.x + threadIdx.x;
    if (idx >= N_NODES * 64) return;
    int n = idx >> 6, cw = idx & 63;
    int c0 = 2 * cw, c1 = c0 + 1;
    float4 xr = ((const float4*)x)[n];
    float v0 = sb[c0] + xr.x * sW[c0] + xr.y * sW[H + c0] + xr.z * sW[2 * H + c0] + xr.w * sW[3 * H + c0];
    float v1 = sb[c1] + xr.x * sW[c1] + xr.y * sW[H + c1] + xr.z * sW[2 * H + c1] + xr.w * sW[3 * H + c1];
    v0 = fmaxf(v0, 0.0f);
    v1 = fmaxf(v1, 0.0f);
    *(float2*)(g_h + (size_t)n * H + c0) = make_float2(v0, v1);
    *(float2*)(g_agg + (size_t)n * H + c0) = make_float2(0.f, 0.f);
    uint32_t hi, lo;
    split_pack(v0, v1, hi, lo);
    g_hB_hi[idx] = hi;
    g_hB_lo[idx] = lo;
}

// ---------------- pack agg to bf16 hi/lo ----------------
__global__ void k_pack_agg() {
    int idx = blockIdx.x * blockDim.x + threadIdx.x;
    if (idx >= N_NODES * 64) return;
    float2 v = ((const float2*)g_agg)[idx];
    uint32_t hi, lo;
    split_pack(v.x, v.y, hi, lo);
    g_aggB_hi[idx] = hi;
    g_aggB_lo[idx] = lo;
}

// ---------------- smem layouts ----------------
#define A_STR 68
#define B_STR 20
#define F_AH 0
#define F_AL (128 * A_STR)
#define F_B  (2 * 128 * A_STR)
#define B_BUF_W (2 * 128 * B_STR)
#define F_META (F_B + 2 * B_BUF_W)
#define EDGE_SMEM ((F_META + 512) * 4)

// GEMM kernels with packed-A: both A and B double-buffered, stride 20
#define P_STR 20
#define PA_BUF_W (2 * 128 * P_STR)    // hi+lo for one chunk buffer
#define PN_A 0
#define PN_B (2 * PA_BUF_W)
#define PN_BIAS (PN_B + 2 * PA_BUF_W)
#define PN_SMEM ((PN_BIAS + 128) * 4)

// ---------------- node precompute: P1/P2 = h @ W1_{top,bot} per type ----------------
__global__ __launch_bounds__(256, 2)
void k_node_pre(int l) {
    extern __shared__ uint32_t smw[];
    const uint32_t su = smem_u32(smw);

    int tid = threadIdx.x;
    int w = tid >> 5, lane = tid & 31;
    int gid = lane >> 2, tig = lane & 3;

    int t = blockIdx.y >> 1, half = blockIdx.y & 1;
    const uint32_t* wbh = g_WPB_hi + ((size_t)(l * NT + t) * 2 + half) * 8192;
    const uint32_t* wbl = g_WPB_lo + ((size_t)(l * NT + t) * 2 + half) * 8192;
    float* C = (half ? g_P2 : g_P1) + (size_t)t * N_NODES * H;

    int m0 = blockIdx.x * 128;
    int row = tid >> 1, off = (tid & 1) * 8;
    int mA = m0 + row; if (mA >= N_NODES) mA = 0;

    // stage chunk 0 into buf 0 (A + B)
    {
        uint32_t da = su + (PN_A + row * P_STR + off) * 4;
        const uint32_t* gah = g_hB_hi + (size_t)mA * 64 + off;
        const uint32_t* gal = g_hB_lo + (size_t)mA * 64 + off;
        cp16(da, gah); cp16(da + 16, gah + 4);
        cp16(da + 128 * P_STR * 4, gal); cp16(da + 128 * P_STR * 4 + 16, gal + 4);
        uint32_t db = su + (PN_B + row * P_STR + off) * 4;
        const uint32_t* gbh = wbh + (size_t)row * 64 + off;
        const uint32_t* gbl = wbl + (size_t)row * 64 + off;
        cp16(db, gbh); cp16(db + 16, gbh + 4);
        cp16(db + 128 * P_STR * 4, gbl); cp16(db + 128 * P_STR * 4 + 16, gbl + 4);
        CP_COMMIT();
    }

    float acc[16][4];
#pragma unroll
    for (int j = 0; j < 16; ++j)
#pragma unroll
        for (int q = 0; q < 4; ++q) acc[j][q] = 0.f;

    int rA0 = w * 16 + gid;
    int rA1 = rA0 + 8;

    for (int kc = 0; kc < 4; ++kc) {
        int buf = kc & 1;
        if (kc < 3) {
            int kn = kc + 1;
            uint32_t da = su + (PN_A + (buf ^ 1) * PA_BUF_W + row * P_STR + off) * 4;
            const uint32_t* gah = g_hB_hi + (size_t)mA * 64 + kn * 16 + off;
            const uint32_t* gal = g_hB_lo + (size_t)mA * 64 + kn * 16 + off;
            cp16(da, gah); cp16(da + 16, gah + 4);
            cp16(da + 128 * P_STR * 4, gal); cp16(da + 128 * P_STR * 4 + 16, gal + 4);
            uint32_t db = su + (PN_B + (buf ^ 1) * PA_BUF_W + row * P_STR + off) * 4;
            const uint32_t* gbh = wbh + (size_t)row * 64 + kn * 16 + off;
            const uint32_t* gbl = wbl + (size_t)row * 64 + kn * 16 + off;
            cp16(db, gbh); cp16(db + 16, gbh + 4);
            cp16(db + 128 * P_STR * 4, gbl); cp16(db + 128 * P_STR * 4 + 16, gbl + 4);
            CP_COMMIT();
            CP_WAIT1();
        } else {
            CP_WAIT0();
        }
        __syncthreads();
        const uint32_t* sAh = smw + PN_A + buf * PA_BUF_W;
        const uint32_t* sAl = sAh + 128 * P_STR;
        const uint32_t* sBh = smw + PN_B + buf * PA_BUF_W;
        const uint32_t* sBl = sBh + 128 * P_STR;
#pragma unroll
        for (int s = 0; s < 2; ++s) {
            int kwb = 8 * s;
            uint32_t ah0 = sAh[rA0 * P_STR + kwb + tig];
            uint32_t ah1 = sAh[rA1 * P_STR + kwb + tig];
            uint32_t ah2 = sAh[rA0 * P_STR + kwb + tig + 4];
            uint32_t ah3 = sAh[rA1 * P_STR + kwb + tig + 4];
            uint32_t al0 = sAl[rA0 * P_STR + kwb + tig];
            uint32_t al1 = sAl[rA1 * P_STR + kwb + tig];
            uint32_t al2 = sAl[rA0 * P_STR + kwb + tig + 4];
            uint32_t al3 = sAl[rA1 * P_STR + kwb + tig + 4];
#pragma unroll
            for (int j = 0; j < 16; ++j) {
                int nb = (j * 8 + gid) * P_STR + kwb + tig;
                uint32_t bh0 = sBh[nb], bh1 = sBh[nb + 4];
                uint32_t bl0 = sBl[nb], bl1 = sBl[nb + 4];
                mma_bf16(acc[j], ah0, ah1, ah2, ah3, bh0, bh1);
                mma_bf16(acc[j], al0, al1, al2, al3, bh0, bh1);
                mma_bf16(acc[j], ah0, ah1, ah2, ah3, bl0, bl1);
            }
        }
        __syncthreads();
    }

    int mg0 = m0 + rA0;
    int mg1 = m0 + rA1;
#pragma unroll
    for (int j = 0; j < 16; ++j) {
        int col = j * 8 + 2 * tig;
        if (mg0 < N_NODES)
            *(float2*)(C + (size_t)mg0 * H + col) = make_float2(acc[j][0], acc[j][1]);
        if (mg1 < N_NODES)
            *(float2*)(C + (size_t)mg1 * H + col) = make_float2(acc[j][2], acc[j][3]);
    }
}

// ---------------- edge kernel (R16 version, unchanged) ----------------
__global__ __launch_bounds__(256, 2)
void k_edge_tc(const int* __restrict__ edge_index,
               const float* __restrict__ b1, const float* __restrict__ b2, int l) {
    extern __shared__ uint32_t smw[];
    uint32_t* sAh = smw + F_AH;
    uint32_t* sAl = smw + F_AL;
    int*   sSrc = (int*)(smw + F_META);
    int*   sDst = sSrc + 128;
    float* sB1  = (float*)(sDst + 128);
    float* sB2  = sB1 + 128;
    const uint32_t su = smem_u32(smw);

    int tid = threadIdx.x;
    int w = tid >> 5, lane = tid & 31;
    int gid = lane >> 2, tig = lane & 3;

    int cnt0 = g_cnt[0];
    int nb0 = (cnt0 + TILE_E - 1) / TILE_E;
    int type, start, cnt, permBase;
    if ((int)blockIdx.x < nb0) {
        type = 0; start = blockIdx.x * TILE_E; cnt = cnt0; permBase = 0;
    } else {
        type = 1; start = ((int)blockIdx.x - nb0) * TILE_E;
        cnt = N_EDGESC - cnt0; permBase = cnt0;
        if (start >= cnt) return;
    }
    int lt = l * NT + type;

    const uint32_t* w2h = g_W2B_hi + (size_t)lt * 8192;
    const uint32_t* w2l = g_W2B_lo + (size_t)lt * 8192;
    const float* P1t = g_P1 + (size_t)type * N_NODES * H;
    const float* P2t = g_P2 + (size_t)type * N_NODES * H;

    int nB = tid >> 1, offB = (tid & 1) * 8;

    {
        uint32_t dst = su + (F_B + nB * B_STR + offB) * 4;
        const uint32_t* gh_ = w2h + nB * 64 + offB;
        const uint32_t* gl_ = w2l + nB * 64 + offB;
        cp16(dst, gh_); cp16(dst + 16, gh_ + 4);
        cp16(dst + 128 * B_STR * 4, gl_); cp16(dst + 128 * B_STR * 4 + 16, gl_ + 4);
        CP_COMMIT();
    }

    if (tid < 128) {
        int g = start + tid; int s = -1, d = -1;
        if (g < cnt) { int e = g_perm[permBase + g]; s = edge_index[e]; d = edge_index[N_EDGESC + e]; }
        sSrc[tid] = s;
        sDst[tid] = d;
    } else {
        int c = tid - 128;
        sB1[c] = b1[lt * H + c];
        sB2[c] = b2[lt * H + c];
    }
    __syncthreads();

    float acc[16][4];
#pragma unroll
    for (int j = 0; j < 16; ++j)
#pragma unroll
        for (int q = 0; q < 4; ++q) acc[j][q] = 0.f;

    int rA0 = w * 16 + gid;
    int rA1 = rA0 + 8;

    int rG[4], qG[4];
#pragma unroll
    for (int i = 0; i < 4; ++i) { int i0 = tid + i * 256; rG[i] = i0 >> 3; qG[i] = i0 & 7; }

    float4 aCur[4], aNxt[4];
#pragma unroll
    for (int i = 0; i < 4; ++i) {
        int s = sSrc[rG[i]], d = sDst[rG[i]];
        if (s >= 0) {
            float4 v1 = *(const float4*)(P1t + (size_t)s * H + qG[i] * 4);
            float4 v2 = *(const float4*)(P2t + (size_t)d * H + qG[i] * 4);
            aCur[i] = make_float4(v1.x + v2.x, v1.y + v2.y, v1.z + v2.z, v1.w + v2.w);
        } else aCur[i] = make_float4(0.f, 0.f, 0.f, 0.f);
    }

    for (int kc = 0; kc < 4; ++kc) {
        int buf = kc & 1;
#pragma unroll
        for (int i = 0; i < 4; ++i) {
            int c4 = kc * 8 + qG[i];
            float4 bb = *(const float4*)(sB1 + c4 * 4);
            bool valid = (sSrc[rG[i]] >= 0);
            float hx = valid ? fmaxf(aCur[i].x + bb.x, 0.f) : 0.f;
            float hy = valid ? fmaxf(aCur[i].y + bb.y, 0.f) : 0.f;
            float hz = valid ? fmaxf(aCur[i].z + bb.z, 0.f) : 0.f;
            float hw = valid ? fmaxf(aCur[i].w + bb.w, 0.f) : 0.f;
            uint32_t h0, l0, h1, l1;
            split_pack(hx, hy, h0, l0);
            split_pack(hz, hw, h1, l1);
            *(uint2*)(sAh + rG[i] * A_STR + kc * 16 + qG[i] * 2) = make_uint2(h0, h1);
            *(uint2*)(sAl + rG[i] * A_STR + kc * 16 + qG[i] * 2) = make_uint2(l0, l1);
        }
        if (kc < 3) {
            int kn = kc + 1;
#pragma unroll
            for (int i = 0; i < 4; ++i) {
                int s = sSrc[rG[i]], d = sDst[rG[i]];
                if (s >= 0) {
                    int c4 = kn * 8 + qG[i];
                    float4 v1 = *(const float4*)(P1t + (size_t)s * H + c4 * 4);
                    float4 v2 = *(const float4*)(P2t + (size_t)d * H + c4 * 4);
                    aNxt[i] = make_float4(v1.x + v2.x, v1.y + v2.y, v1.z + v2.z, v1.w + v2.w);
                } else aNxt[i] = make_float4(0.f, 0.f, 0.f, 0.f);
            }
            uint32_t dst = su + (F_B + (buf ^ 1) * B_BUF_W + nB * B_STR + offB) * 4;
            const uint32_t* gh_ = w2h + nB * 64 + kn * 16 + offB;
            const uint32_t* gl_ = w2l + nB * 64 + kn * 16 + offB;
            cp16(dst, gh_); cp16(dst + 16, gh_ + 4);
            cp16(dst + 128 * B_STR * 4, gl_); cp16(dst + 128 * B_STR * 4 + 16, gl_ + 4);
            CP_COMMIT();
            CP_WAIT1();
        } else {
            CP_WAIT0();
        }
        __syncthreads();
        const uint32_t* sBh = smw + F_B + buf * B_BUF_W;
        const uint32_t* sBl = sBh + 128 * B_STR;
#pragma unroll
        for (int s = 0; s < 2; ++s) {
            int kwb = kc * 16 + 8 * s;
            uint32_t ah0 = sAh[rA0 * A_STR + kwb + tig];
            uint32_t ah1 = sAh[rA1 * A_STR + kwb + tig];
            uint32_t ah2 = sAh[rA0 * A_STR + kwb + tig + 4];
            uint32_t ah3 = sAh[rA1 * A_STR + kwb + tig + 4];
            uint32_t al0 = sAl[rA0 * A_STR + kwb + tig];
            uint32_t al1 = sAl[rA1 * A_STR + kwb + tig];
            uint32_t al2 = sAl[rA0 * A_STR + kwb + tig + 4];
            uint32_t al3 = sAl[rA1 * A_STR + kwb + tig + 4];
#pragma unroll
            for (int j = 0; j < 16; ++j) {
                int nb = (j * 8 + gid) * B_STR + 8 * s + tig;
                uint32_t bh0 = sBh[nb], bh1 = sBh[nb + 4];
                uint32_t bl0 = sBl[nb], bl1 = sBl[nb + 4];
                mma_bf16(acc[j], ah0, ah1, ah2, ah3, bh0, bh1);
                mma_bf16(acc[j], al0, al1, al2, al3, bh0, bh1);
                mma_bf16(acc[j], ah0, ah1, ah2, ah3, bl0, bl1);
            }
        }
        __syncthreads();
#pragma unroll
        for (int i = 0; i < 4; ++i) aCur[i] = aNxt[i];
    }

    int d0 = sDst[rA0];
    int d1 = sDst[rA1];
#pragma unroll
    for (int j = 0; j < 16; ++j) {
        int col = j * 8 + 2 * tig;
        float ba = sB2[col], bb = sB2[col + 1];
        if (d0 >= 0) red2(g_agg + (size_t)d0 * H + col, acc[j][0] + ba, acc[j][1] + bb);
        if (d1 >= 0) red2(g_agg + (size_t)d1 * H + col, acc[j][2] + ba, acc[j][3] + bb);
    }
}

// ---------------- GRU GEMMs: packed A via cp.async ----------------
__global__ __launch_bounds__(256, 2)
void k_gru_tc(const float* __restrict__ bih, const float* __restrict__ bhh, int l) {
    extern __shared__ uint32_t smw[];
    float* sBias = (float*)(smw + PN_BIAS);
    const uint32_t su = smem_u32(smw);

    int tid = threadIdx.x;
    int w = tid >> 5, lane = tid & 31;
    int gid = lane >> 2, tig = lane & 3;

    int sel = blockIdx.z;
    const uint32_t* aH = sel ? g_hB_hi : g_aggB_hi;
    const uint32_t* aL = sel ? g_hB_lo : g_aggB_lo;
    float* C = sel ? g_gh : g_gi;
    const float* b = (sel ? bhh : bih) + l * 3 * H;
    const uint32_t* wbh = g_WGB_hi + ((size_t)sel * 3 + l) * 24576;
    const uint32_t* wbl = g_WGB_lo + ((size_t)sel * 3 + l) * 24576;

    int m0 = blockIdx.x * 128;
    int c0 = blockIdx.y * 128;

    int row = tid >> 1, off = (tid & 1) * 8;
    int mA = m0 + row; if (mA >= N_NODES) mA = 0;

    {
        uint32_t da = su + (PN_A + row * P_STR + off) * 4;
        const uint32_t* gah = aH + (size_t)mA * 64 + off;
        const uint32_t* gal = aL + (size_t)mA * 64 + off;
        cp16(da, gah); cp16(da + 16, gah + 4);
        cp16(da + 128 * P_STR * 4, gal); cp16(da + 128 * P_STR * 4 + 16, gal + 4);
        uint32_t db = su + (PN_B + row * P_STR + off) * 4;
        const uint32_t* gbh = wbh + (size_t)(c0 + row) * 64 + off;
        const uint32_t* gbl = wbl + (size_t)(c0 + row) * 64 + off;
        cp16(db, gbh); cp16(db + 16, gbh + 4);
        cp16(db + 128 * P_STR * 4, gbl); cp16(db + 128 * P_STR * 4 + 16, gbl + 4);
        CP_COMMIT();
    }

    if (tid < 128) sBias[tid] = b[c0 + tid];

    float acc[16][4];
#pragma unroll
    for (int j = 0; j < 16; ++j)
#pragma unroll
        for (int q = 0; q < 4; ++q) acc[j][q] = 0.f;

    int rA0 = w * 16 + gid;
    int rA1 = rA0 + 8;

    for (int kc = 0; kc < 4; ++kc) {
        int buf = kc & 1;
        if (kc < 3) {
            int kn = kc + 1;
            uint32_t da = su + (PN_A + (buf ^ 1) * PA_BUF_W + row * P_STR + off) * 4;
            const uint32_t* gah = aH + (size_t)mA * 64 + kn * 16 + off;
            const uint32_t* gal = aL + (size_t)mA * 64 + kn * 16 + off;
            cp16(da, gah); cp16(da + 16, gah + 4);
            cp16(da + 128 * P_STR * 4, gal); cp16(da + 128 * P_STR * 4 + 16, gal + 4);
            uint32_t db = su + (PN_B + (buf ^ 1) * PA_BUF_W + row * P_STR + off) * 4;
            const uint32_t* gbh = wbh + (size_t)(c0 + row) * 64 + kn * 16 + off;
            const uint32_t* gbl = wbl + (size_t)(c0 + row) * 64 + kn * 16 + off;
            cp16(db, gbh); cp16(db + 16, gbh + 4);
            cp16(db + 128 * P_STR * 4, gbl); cp16(db + 128 * P_STR * 4 + 16, gbl + 4);
            CP_COMMIT();
            CP_WAIT1();
        } else {
            CP_WAIT0();
        }
        __syncthreads();
        const uint32_t* sAh = smw + PN_A + buf * PA_BUF_W;
        const uint32_t* sAl = sAh + 128 * P_STR;
        const uint32_t* sBh = smw + PN_B + buf * PA_BUF_W;
        const uint32_t* sBl = sBh + 128 * P_STR;
#pragma unroll
        for (int s = 0; s < 2; ++s) {
            int kwb = 8 * s;
            uint32_t ah0 = sAh[rA0 * P_STR + kwb + tig];
            uint32_t ah1 = sAh[rA1 * P_STR + kwb + tig];
            uint32_t ah2 = sAh[rA0 * P_STR + kwb + tig + 4];
            uint32_t ah3 = sAh[rA1 * P_STR + kwb + tig + 4];
            uint32_t al0 = sAl[rA0 * P_STR + kwb + tig];
            uint32_t al1 = sAl[rA1 * P_STR + kwb + tig];
            uint32_t al2 = sAl[rA0 * P_STR + kwb + tig + 4];
            uint32_t al3 = sAl[rA1 * P_STR + kwb + tig + 4];
#pragma unroll
            for (int j = 0; j < 16; ++j) {
                int nb = (j * 8 + gid) * P_STR + kwb + tig;
                uint32_t bh0 = sBh[nb], bh1 = sBh[nb + 4];
                uint32_t bl0 = sBl[nb], bl1 = sBl[nb + 4];
                mma_bf16(acc[j], ah0, ah1, ah2, ah3, bh0, bh1);
                mma_bf16(acc[j], al0, al1, al2, al3, bh0, bh1);
                mma_bf16(acc[j], ah0, ah1, ah2, ah3, bl0, bl1);
            }
        }
        __syncthreads();
    }

    int mg0 = m0 + rA0;
    int mg1 = m0 + rA1;
#pragma unroll
    for (int j = 0; j < 16; ++j) {
        int col = j * 8 + 2 * tig;
        float ba = sBias[col], bb = sBias[col + 1];
        if (mg0 < N_NODES)
            *(float2*)(C + (size_t)mg0 * 384 + c0 + col) =
                make_float2(acc[j][0] + ba, acc[j][1] + bb);
        if (mg1 < N_NODES)
            *(float2*)(C + (size_t)mg1 * 384 + c0 + col) =
                make_float2(acc[j][2] + ba, acc[j][3] + bb);
    }
}

// ---------------- GRU combine: 2 elems/thread, pack h, zero agg ----------------
__global__ void k_gru_combine() {
    int idx = blockIdx.x * blockDim.x + threadIdx.x;
    if (idx >= N_NODES * 64) return;
    int n = idx >> 6, cw = idx & 63;
    int c = cw * 2;
    const float* gi = g_gi + (size_t)n * 384;
    const float* gh = g_gh + (size_t)n * 384;
    float2 gir = *(const float2*)(gi + c);
    float2 giz = *(const float2*)(gi + 128 + c);
    float2 gin = *(const float2*)(gi + 256 + c);
    float2 ghr = *(const float2*)(gh + c);
    float2 ghz = *(const float2*)(gh + 128 + c);
    float2 ghn = *(const float2*)(gh + 256 + c);
    float2 hv = *(const float2*)(g_h + (size_t)n * H + c);
    float r0 = sigm(gir.x + ghr.x), r1 = sigm(gir.y + ghr.y);
    float z0 = sigm(giz.x + ghz.x), z1 = sigm(giz.y + ghz.y);
    float n0 = tanhf(gin.x + r0 * ghn.x), n1 = tanhf(gin.y + r1 * ghn.y);
    float h0 = (1.f - z0) * n0 + z0 * hv.x;
    float h1 = (1.f - z1) * n1 + z1 * hv.y;
    *(float2*)(g_h + (size_t)n * H + c) = make_float2(h0, h1);
    *(float2*)(g_agg + (size_t)n * H + c) = make_float2(0.f, 0.f);
    uint32_t hi, lo;
    split_pack(h0, h1, hi, lo);
    g_hB_hi[idx] = hi;
    g_hB_lo[idx] = lo;
}

// ---------------- readout ----------------
__global__ __launch_bounds__(256)
void k_readout(const float* __restrict__ Wr1, const float* __restrict__ br1,
               const float* __restrict__ Wr2, const float* __restrict__ br2,
               float* __restrict__ out, int nd) {
    extern __shared__ float smemf[];
    float* sW1 = smemf;
    float* sb1 = sW1 + H * H;
    float* sW2 = sb1 + H;
    float* sHrow = sW2 + H;

    for (int t = threadIdx.x; t < (H * H) / 4; t += blockDim.x)
        ((float4*)sW1)[t] = ((const float4*)Wr1)[t];
    if (threadIdx.x < H) {
        sb1[threadIdx.x] = br1[threadIdx.x];
        sW2[threadIdx.x] = Wr2[threadIdx.x];
    }
    __syncthreads();

    int w = threadIdx.x >> 5, lane = threadIdx.x & 31;
    float* myrow = sHrow + w * H;
    float b2v = br2[0];

    for (int n = blockIdx.x * 8 + w; n < nd; n += gridDim.x * 8) {
        ((float4*)myrow)[lane] = ((const float4*)(g_h + (size_t)n * H))[lane];
        __syncwarp();
        float hid0 = 0.f, hid1 = 0.f, hid2 = 0.f, hid3 = 0.f;
#pragma unroll 4
        for (int k = 0; k < H; ++k) {
            float a = myrow[k];
            float4 wv = ((const float4*)sW1)[k * 32 + lane];
            hid0 += a * wv.x; hid1 += a * wv.y; hid2 += a * wv.z; hid3 += a * wv.w;
        }
        float4 w2 = ((const float4*)sW2)[lane];
        float p = fmaxf(hid0 + sb1[lane * 4 + 0], 0.f) * w2.x
                + fmaxf(hid1 + sb1[lane * 4 + 1], 0.f) * w2.y
                + fmaxf(hid2 + sb1[lane * 4 + 2], 0.f) * w2.z
                + fmaxf(hid3 + sb1[lane * 4 + 3], 0.f) * w2.w;
#pragma unroll
        for (int o = 16; o > 0; o >>= 1) p += __shfl_down_sync(0xffffffffu, p, o);
        if (lane == 0) out[n] = p + b2v;
        __syncwarp();
    }
}

// ---------------- launch ----------------
extern "C" void kernel_launch(void* const* d_in, const int* in_sizes, int n_in,
                              void* d_out, int out_size) {
    int base = (n_in >= 18) ? 4 : 3;
    const float* x          = (const float*)d_in[0];
    const int*   edge_index = (const int*)d_in[1];
    const int*   edge_type  = (const int*)d_in[2];
    const float* W_in = (const float*)d_in[base + 0];
    const float* b_in = (const float*)d_in[base + 1];
    const float* W1   = (const float*)d_in[base + 2];
    const float* b1   = (const float*)d_in[base + 3];
    const float* W2   = (const float*)d_in[base + 4];
    const float* b2   = (const float*)d_in[base + 5];
    const float* W_ih = (const float*)d_in[base + 6];
    const float* b_ih = (const float*)d_in[base + 7];
    const float* W_hh = (const float*)d_in[base + 8];
    const float* b_hh = (const float*)d_in[base + 9];
    const float* Wr1  = (const float*)d_in[base + 10];
    const float* br1  = (const float*)d_in[base + 11];
    const float* Wr2  = (const float*)d_in[base + 12];
    const float* br2  = (const float*)d_in[base + 13];
    float* out = (float*)d_out;

    const int READ_SMEM = (128 * 128 + 128 + 128 + 8 * 128) * 4;
    cudaFuncSetAttribute(k_edge_tc,  cudaFuncAttributeMaxDynamicSharedMemorySize, EDGE_SMEM);
    cudaFuncSetAttribute(k_node_pre, cudaFuncAttributeMaxDynamicSharedMemorySize, PN_SMEM);
    cudaFuncSetAttribute(k_gru_tc,   cudaFuncAttributeMaxDynamicSharedMemorySize, PN_SMEM);
    cudaFuncSetAttribute(k_readout,  cudaFuncAttributeMaxDynamicSharedMemorySize, READ_SMEM);

    k_zero_cnt<<<1, 32>>>();
    k_count<<<(N_EDGESC + 255) / 256, 256>>>(edge_type);
    k_seed<<<1, 1>>>();
    k_scatter<<<(N_EDGESC + 255) / 256, 256>>>(edge_type);

    const int NPW = 6 * 2 * 128 * 64 + 6 * 128 * 64;
    k_prep_w<<<(NPW + 255) / 256, 256>>>(W1, W2);
    k_prep_gru<<<(2 * 3 * 384 * 64 + 255) / 256, 256>>>(W_ih, W_hh);
    const int NHW = N_NODES * 64;
    k_init<<<(NHW + 255) / 256, 256>>>(x, W_in, b_in);

    const int EDGE_BLOCKS = N_EDGESC / TILE_E + 2;
    for (int l = 0; l < 3; ++l) {
        dim3 gp((N_NODES + 127) / 128, 4);
        k_node_pre<<<gp, 256, PN_SMEM>>>(l);
        k_edge_tc<<<EDGE_BLOCKS, 256, EDGE_SMEM>>>(edge_index, b1, b2, l);
        k_pack_agg<<<(NHW + 255) / 256, 256>>>();
        dim3 gg((N_NODES + 127) / 128, 3, 2);
        k_gru_tc<<<gg, 256, PN_SMEM>>>(b_ih, b_hh, l);
        k_gru_combine<<<(NHW + 255) / 256, 256>>>();
    }

    k_readout<<<625, 256, READ_SMEM>>>(Wr1, br1, Wr2, br2, out, out_size);
}